// round 13
// baseline (speedup 1.0000x reference)
#include <cuda_runtime.h>

#define BB 32
#define RR 512
#define TT 128
#define HH 64

typedef unsigned long long ull;

// ---- scratch (device globals; no allocations) ----
__device__ float g_k [BB*RR*HH];
__device__ float g_v [BB*RR*HH];
__device__ float g_rp[BB*RR*HH];
__device__ float g_q [BB*TT*HH];
__device__ float g_tp[BB*TT*HH];

// ---- packed fp32x2 helpers (Blackwell FFMA2 path) ----
__device__ __forceinline__ ull pack2(float a) {
    ull r;
    asm("mov.b64 %0, {%1, %1};" : "=l"(r) : "f"(a));
    return r;
}
__device__ __forceinline__ void fma2(ull& d, ull a, ull b) {
    asm("fma.rn.f32x2 %0, %1, %2, %0;" : "+l"(d) : "l"(a), "l"(b));
}
__device__ __forceinline__ float2 unpack2(ull v) {
    float2 f;
    asm("mov.b64 {%0, %1}, %2;" : "=f"(f.x), "=f"(f.y) : "l"(v));
    return f;
}

// =====================================================================
// Kernel 1: merged encoders (unchanged from round 12).
// =====================================================================
__global__ void __launch_bounds__(256) k_enc(
    const float* __restrict__ xr_, const float* __restrict__ xt_,
    const float* __restrict__ rw1, const float* __restrict__ rb1,
    const float* __restrict__ rw2, const float* __restrict__ rb2,
    const float* __restrict__ tw1, const float* __restrict__ tb1,
    const float* __restrict__ tw2, const float* __restrict__ tb2,
    const float* __restrict__ wq, const float* __restrict__ bq,
    const float* __restrict__ wk, const float* __restrict__ bk,
    const float* __restrict__ wv, const float* __restrict__ bv,
    const float* __restrict__ aw1)
{
    __shared__ float sA[8][4][64];
    __shared__ float sB[8][4][64];
    int wid = threadIdx.x >> 5, lane = threadIdx.x & 31;
    int c = lane * 2;

    if (blockIdx.x < 512) {
        int r0 = blockIdx.x * 32 + wid * 4;
        const float* xp = xr_ + r0 * 7;
        float xv[4][7];
#pragma unroll
        for (int rr = 0; rr < 4; rr++)
#pragma unroll
            for (int i = 0; i < 7; i++) xv[rr][i] = xp[rr*7 + i];

        float2 b1v = *(const float2*)&rb1[c];
        float h[4][2];
#pragma unroll
        for (int rr = 0; rr < 4; rr++) { h[rr][0] = b1v.x; h[rr][1] = b1v.y; }
#pragma unroll
        for (int i = 0; i < 7; i++) {
            float2 w = *(const float2*)&rw1[i*64 + c];
#pragma unroll
            for (int rr = 0; rr < 4; rr++) { h[rr][0] += xv[rr][i]*w.x; h[rr][1] += xv[rr][i]*w.y; }
        }
#pragma unroll
        for (int rr = 0; rr < 4; rr++) {
            sA[wid][rr][c]   = fmaxf(h[rr][0], 0.f);
            sA[wid][rr][c+1] = fmaxf(h[rr][1], 0.f);
        }
        __syncwarp();

        float2 b2v = *(const float2*)&rb2[c];
        float g[4][2];
#pragma unroll
        for (int rr = 0; rr < 4; rr++) { g[rr][0] = b2v.x; g[rr][1] = b2v.y; }
#pragma unroll 4
        for (int j = 0; j < 64; j++) {
            float2 w = *(const float2*)&rw2[j*64 + c];
#pragma unroll
            for (int rr = 0; rr < 4; rr++) {
                float s = sA[wid][rr][j];
                g[rr][0] += s*w.x; g[rr][1] += s*w.y;
            }
        }
#pragma unroll
        for (int rr = 0; rr < 4; rr++) {
            sB[wid][rr][c]   = fmaxf(g[rr][0], 0.f);
            sB[wid][rr][c+1] = fmaxf(g[rr][1], 0.f);
        }
        __syncwarp();

        float2 bkv = *(const float2*)&bk[c];
        float2 bvv = *(const float2*)&bv[c];
        float ka[4][2], va[4][2], pa[4][2];
#pragma unroll
        for (int rr = 0; rr < 4; rr++) {
            ka[rr][0] = bkv.x; ka[rr][1] = bkv.y;
            va[rr][0] = bvv.x; va[rr][1] = bvv.y;
            pa[rr][0] = 0.f;   pa[rr][1] = 0.f;
        }
#pragma unroll 2
        for (int j = 0; j < 64; j++) {
            float2 wkj = *(const float2*)&wk[j*64 + c];
            float2 wvj = *(const float2*)&wv[j*64 + c];
            float2 waj = *(const float2*)&aw1[(64+j)*64 + c];
#pragma unroll
            for (int rr = 0; rr < 4; rr++) {
                float s = sB[wid][rr][j];
                ka[rr][0] += s*wkj.x; ka[rr][1] += s*wkj.y;
                va[rr][0] += s*wvj.x; va[rr][1] += s*wvj.y;
                pa[rr][0] += s*waj.x; pa[rr][1] += s*waj.y;
            }
        }
#pragma unroll
        for (int rr = 0; rr < 4; rr++) {
            int gr = r0 + rr;
            *(float2*)&g_k [gr*64 + c] = make_float2(ka[rr][0], ka[rr][1]);
            *(float2*)&g_v [gr*64 + c] = make_float2(va[rr][0], va[rr][1]);
            *(float2*)&g_rp[gr*64 + c] = make_float2(pa[rr][0], pa[rr][1]);
        }
    } else {
        int row = (blockIdx.x - 512) * 8 + wid;
        const float* xr = xt_ + row * 6;
        float xv[6];
#pragma unroll
        for (int i = 0; i < 6; i++) xv[i] = xr[i];

        float ha = tb1[c], hb = tb1[c+1];
#pragma unroll
        for (int i = 0; i < 6; i++) {
            float2 w = *(const float2*)&tw1[i*64 + c];
            ha += xv[i]*w.x; hb += xv[i]*w.y;
        }
        sA[wid][0][c] = fmaxf(ha, 0.f); sA[wid][0][c+1] = fmaxf(hb, 0.f);
        __syncwarp();

        float ga = tb2[c], gb = tb2[c+1];
#pragma unroll 8
        for (int j = 0; j < 64; j++) {
            float2 w = *(const float2*)&tw2[j*64 + c];
            float s = sA[wid][0][j];
            ga += s*w.x; gb += s*w.y;
        }
        sB[wid][0][c] = fmaxf(ga, 0.f); sB[wid][0][c+1] = fmaxf(gb, 0.f);
        __syncwarp();

        float qa = bq[c], qb = bq[c+1];
#pragma unroll 8
        for (int j = 0; j < 64; j++) {
            float2 w = *(const float2*)&wq[j*64 + c];
            float s = sB[wid][0][j];
            qa += s*w.x; qb += s*w.y;
        }
        g_q[row*64 + c] = qa; g_q[row*64 + c+1] = qb;
    }
}

// =====================================================================
// Kernel 3: attention, 8 tasks per block (grid = 512), 256 thr (unchanged)
// =====================================================================
#define AQ   0
#define ALG  512
#define AKV  16896
#define AINV 25600
#define ACS  25632
#define ATF  26144
#define ATTN_SMEM_FLOATS 26656

__global__ void __launch_bounds__(256) k_attn(
    const float* __restrict__ wo, const float* __restrict__ bo,
    const float* __restrict__ aw1, const float* __restrict__ ab1)
{
    extern __shared__ float sm[];
    int blk = blockIdx.x;
    int b = blk >> 4;
    int tk0 = (blk & 15) * 8;
    int t = threadIdx.x, lane = t & 31, w = t >> 5;

    for (int i = t; i < 512; i += 256)
        sm[AQ + i] = g_q[(size_t)(b*128 + tk0 + (i >> 6))*64 + (i & 63)];

    const float* kb = g_k + (size_t)b*RR*64;
    const float* vb = g_v + (size_t)b*RR*64;

    for (int chunk = 0; chunk < 4; chunk++) {
        __syncthreads();
#pragma unroll
        for (int i = 0; i < 8; i++) {
            int lin = t + i*256;
            int row = lin >> 4, c4 = lin & 15;
            float4 kvv = *(const float4*)(kb + (size_t)(chunk*128 + row)*64 + c4*4);
            *(float4*)&sm[AKV + row*68 + c4*4] = kvv;
        }
        __syncthreads();
#pragma unroll
        for (int i = 0; i < 16; i++) {
            int idx = i*256 + t;
            int th = idx >> 7, r = idx & 127;
            int task = th >> 2, h = th & 3;
            const float* kr = &sm[AKV + r*68 + h*16];
            const float* qh = &sm[AQ + task*64 + h*16];
            float d = 0.f;
#pragma unroll
            for (int j = 0; j < 16; j += 4) {
                float4 kv4 = *(const float4*)(kr + j);
                float4 q4  = *(const float4*)(qh + j);
                d += kv4.x*q4.x + kv4.y*q4.y + kv4.z*q4.z + kv4.w*q4.w;
            }
            sm[ALG + (task*4 + h)*512 + chunk*128 + r] = d * 0.25f;
        }
    }
    __syncthreads();

    for (int p = w; p < 32; p += 8) {
        float* base = &sm[ALG + p*512];
        float v[16];
        float m = -1e30f;
#pragma unroll
        for (int i = 0; i < 16; i++) { v[i] = base[i*32 + lane]; m = fmaxf(m, v[i]); }
#pragma unroll
        for (int o = 16; o; o >>= 1) m = fmaxf(m, __shfl_xor_sync(0xffffffffu, m, o));
        float s = 0.f;
#pragma unroll
        for (int i = 0; i < 16; i++) {
            float e = __expf(v[i] - m);
            base[i*32 + lane] = e;
            s += e;
        }
#pragma unroll
        for (int o = 16; o; o >>= 1) s += __shfl_xor_sync(0xffffffffu, s, o);
        if (lane == 0) sm[AINV + p] = 1.f / s;
    }
    __syncthreads();

    int task = t >> 5;
    int c2 = (t & 31) * 2;
    int hh = c2 >> 4;
    float acc0 = 0.f, acc1 = 0.f;
    for (int chunk = 0; chunk < 4; chunk++) {
        __syncthreads();
#pragma unroll
        for (int i = 0; i < 8; i++) {
            int lin = t + i*256;
            int row = lin >> 4, c4 = lin & 15;
            float4 vvv = *(const float4*)(vb + (size_t)(chunk*128 + row)*64 + c4*4);
            *(float4*)&sm[AKV + row*68 + c4*4] = vvv;
        }
        __syncthreads();
        const float* lgp = &sm[ALG + (task*4 + hh)*512 + chunk*128];
#pragma unroll 4
        for (int r = 0; r < 128; r++) {
            float a = lgp[r];
            float2 vv = *(const float2*)&sm[AKV + r*68 + c2];
            acc0 += a*vv.x; acc1 += a*vv.y;
        }
    }
    __syncthreads();

    {
        float inv = sm[AINV + task*4 + hh];
        sm[ACS + task*64 + c2]     = acc0 * inv;
        sm[ACS + task*64 + c2 + 1] = acc1 * inv;
    }
#pragma unroll
    for (int i = 0; i < 4; i++) {
        int lin = t + i*256;
        *(float4*)&sm[AKV + lin*4]        = *(const float4*)(wo  + lin*4);
        *(float4*)&sm[AKV + 4096 + lin*4] = *(const float4*)(aw1 + lin*4);
    }
    __syncthreads();

    {
        int c = lane * 2;
        float2 bov = *(const float2*)&bo[c];
        float f0 = bov.x, f1 = bov.y;
#pragma unroll 8
        for (int j = 0; j < 64; j++) {
            float s = sm[ACS + w*64 + j];
            float2 ww = *(const float2*)&sm[AKV + j*64 + c];
            f0 += s*ww.x; f1 += s*ww.y;
        }
        sm[ATF + w*64 + c] = f0; sm[ATF + w*64 + c + 1] = f1;
        __syncwarp();
        float2 abv = *(const float2*)&ab1[c];
        float p0 = abv.x, p1 = abv.y;
#pragma unroll 8
        for (int j = 0; j < 64; j++) {
            float s = sm[ATF + w*64 + j];
            float2 ww = *(const float2*)&sm[AKV + 4096 + j*64 + c];
            p0 += s*ww.x; p1 += s*ww.y;
        }
        *(float2*)&g_tp[(size_t)(b*128 + tk0 + w)*64 + c] = make_float2(p0, p1);
    }
}

// =====================================================================
// Kernel 4 (dominant): pairwise MLP + softmax. block per (b,t).
// 256 THREADS (was 128): same 2-CTA/SM smem footprint but 16 warps/SM
// (4/SMSP) -> hides LDS/FMA latency that capped rounds 6-12 at ~200us.
// 2 tiles of 256 robots; thread tile 4 rows (ty+64m) x 8 cols.
// smem (floats): W2 0(2048) | b2 2048(32) | w3 2080(32) | tp 2112(64)
//   h1s 2176(256*68=17408) | sp 19584(4*260=1040) | sc 20624(512)
//   red 21136(16)  total 21152 fl = 84608 B
// =====================================================================
#define SW2  0
#define SB2  2048
#define SW3  2080
#define STP  2112
#define SH1  2176
#define SSP  19584
#define SSC  20624
#define SRED 21136
#define PAIR_SMEM_FLOATS 21152

__global__ void __launch_bounds__(256) k_pair(
    const float* __restrict__ aw2, const float* __restrict__ ab2,
    const float* __restrict__ aw3, float* __restrict__ out)
{
    extern __shared__ float sm[];
    int bt = blockIdx.x;
    int b  = bt >> 7;
    int t = threadIdx.x, lane = t & 31, wid = t >> 5;

    for (int i = t; i < 2048; i += 256) sm[SW2 + i] = aw2[i];
    if (t < 32) { sm[SB2 + t] = ab2[t]; sm[SW3 + t] = aw3[t]; }
    if (t >= 64 && t < 128) sm[STP + t - 64] = g_tp[bt*64 + t - 64];
    __syncthreads();

    int tx = t & 3;          // col group: cols tx*8 .. +7 (4 col pairs)
    int ty = t >> 2;         // 0..63 -> rows ty + 64m, m=0..3
    int j4b = t & 15;        // build: fixed column quad per thread
    int rrb = t >> 4;        // build: base row (0..15)
    const float* rpb = g_rp + (size_t)b*RR*64;
    float4 tv = *(const float4*)&sm[STP + j4b*4];

    for (int tile = 0; tile < 2; tile++) {
        int r0 = tile * 256;
        // ---- build h1s[rr][j]: relu(tp + rp), 256 rows x 64 cols ----
#pragma unroll 4
        for (int i = 0; i < 16; i++) {
            int rr = rrb + i*16;
            float4 rv = *(const float4*)(rpb + (size_t)(r0 + rr)*64 + j4b*4);
            float4 hv;
            hv.x = fmaxf(rv.x + tv.x, 0.f);
            hv.y = fmaxf(rv.y + tv.y, 0.f);
            hv.z = fmaxf(rv.z + tv.z, 0.f);
            hv.w = fmaxf(rv.w + tv.w, 0.f);
            *(float4*)&sm[SH1 + rr*68 + j4b*4] = hv;
        }
        __syncthreads();

        // ---- GEMM: [256 x 32] = h1[256 x 64] @ W2[64 x 32] ----
        ull acc[4][4];
#pragma unroll
        for (int m = 0; m < 4; m++)
#pragma unroll
            for (int cc = 0; cc < 4; cc++)
                acc[m][cc] = *(const ull*)&sm[SB2 + tx*8 + cc*2];

#pragma unroll 4
        for (int j4 = 0; j4 < 16; j4++) {
            float Aa[4][4];
#pragma unroll
            for (int m = 0; m < 4; m++)
                *(float4*)Aa[m] = *(const float4*)&sm[SH1 + (ty + 64*m)*68 + j4*4];
#pragma unroll
            for (int kk = 0; kk < 4; kk++) {
                const ulonglong2* wp = (const ulonglong2*)&sm[SW2 + (j4*4 + kk)*32 + tx*8];
                ulonglong2 w01 = wp[0], w23 = wp[1];
#pragma unroll
                for (int m = 0; m < 4; m++) {
                    ull a2 = pack2(Aa[m][kk]);
                    fma2(acc[m][0], a2, w01.x); fma2(acc[m][1], a2, w01.y);
                    fma2(acc[m][2], a2, w23.x); fma2(acc[m][3], a2, w23.y);
                }
            }
        }

        // ---- epilogue: relu(h2) . a_w3 (a_b3 cancels in softmax) ----
#pragma unroll
        for (int m = 0; m < 4; m++) {
            float p = 0.f;
#pragma unroll
            for (int cc = 0; cc < 4; cc++) {
                float2 f = unpack2(acc[m][cc]);
                p += fmaxf(f.x, 0.f) * sm[SW3 + tx*8 + 2*cc]
                   + fmaxf(f.y, 0.f) * sm[SW3 + tx*8 + 2*cc + 1];
            }
            sm[SSP + tx*260 + ty + 64*m] = p;
        }
        __syncthreads();
        sm[SSC + r0 + t] = sm[SSP + t] + sm[SSP + 260 + t] + sm[SSP + 520 + t] + sm[SSP + 780 + t];
        __syncthreads();
    }

    // ---- softmax over 512 robots (256 threads, 2 values each) ----
    float v0 = sm[SSC + t], v1 = sm[SSC + t + 256];
    float m = fmaxf(v0, v1);
#pragma unroll
    for (int o = 16; o; o >>= 1) m = fmaxf(m, __shfl_xor_sync(0xffffffffu, m, o));
    if (lane == 0) sm[SRED + wid] = m;
    __syncthreads();
    m = sm[SRED + 0];
#pragma unroll
    for (int i = 1; i < 8; i++) m = fmaxf(m, sm[SRED + i]);
    v0 = __expf(v0 - m); v1 = __expf(v1 - m);
    float s = v0 + v1;
#pragma unroll
    for (int o = 16; o; o >>= 1) s += __shfl_xor_sync(0xffffffffu, s, o);
    if (lane == 0) sm[SRED + 8 + wid] = s;
    __syncthreads();
    s = sm[SRED + 8];
#pragma unroll
    for (int i = 1; i < 8; i++) s += sm[SRED + 8 + i];
    float inv = 1.f / s;
    float* op = out + (size_t)bt * 512;
    op[t]       = v0 * inv;
    op[t + 256] = v1 * inv;
}

// =====================================================================
extern "C" void kernel_launch(void* const* d_in, const int* in_sizes, int n_in,
                              void* d_out, int out_size)
{
    (void)in_sizes; (void)n_in; (void)out_size;
    const float* robot = (const float*)d_in[0];
    const float* task  = (const float*)d_in[1];
    const float* r_w1  = (const float*)d_in[2];
    const float* r_b1  = (const float*)d_in[3];
    const float* r_w2  = (const float*)d_in[4];
    const float* r_b2  = (const float*)d_in[5];
    const float* t_w1  = (const float*)d_in[6];
    const float* t_b1  = (const float*)d_in[7];
    const float* t_w2  = (const float*)d_in[8];
    const float* t_b2  = (const float*)d_in[9];
    const float* wq    = (const float*)d_in[10];
    const float* bq    = (const float*)d_in[11];
    const float* wk    = (const float*)d_in[12];
    const float* bk    = (const float*)d_in[13];
    const float* wv    = (const float*)d_in[14];
    const float* bv    = (const float*)d_in[15];
    const float* wo    = (const float*)d_in[16];
    const float* bo    = (const float*)d_in[17];
    const float* a_w1  = (const float*)d_in[18];
    const float* a_b1  = (const float*)d_in[19];
    const float* a_w2  = (const float*)d_in[20];
    const float* a_b2  = (const float*)d_in[21];
    const float* a_w3  = (const float*)d_in[22];

    static_assert(ATTN_SMEM_FLOATS * 4 < 230000, "attn smem");
    static_assert(PAIR_SMEM_FLOATS * 4 < 114000, "pair smem (2 CTA/SM)");
    cudaFuncSetAttribute(k_attn, cudaFuncAttributeMaxDynamicSharedMemorySize, ATTN_SMEM_FLOATS * 4);
    cudaFuncSetAttribute(k_pair, cudaFuncAttributeMaxDynamicSharedMemorySize, PAIR_SMEM_FLOATS * 4);

    k_enc <<<1024, 256>>>(robot, task, r_w1, r_b1, r_w2, r_b2,
                          t_w1, t_b1, t_w2, t_b2, wq, bq, wk, bk, wv, bv, a_w1);
    k_attn<<<BB*16, 256, ATTN_SMEM_FLOATS * 4>>>(wo, bo, a_w1, a_b1);
    k_pair<<<BB*TT, 256, PAIR_SMEM_FLOATS * 4>>>(a_w2, a_b2, a_w3, (float*)d_out);
}